// round 3
// baseline (speedup 1.0000x reference)
#include <cuda_runtime.h>
#include <math.h>

// ---------------------------------------------------------------------------
// GAT pipeline (atomic-free aggregation via dst-CSR gather):
//   detect:   edge_index dtype sniff (JAX x64-disabled -> int32 silently)
//   prep:     fused weight matrices + attention vectors + zero deg
//   gemm_big: [N,512] @ [512,160] -> xl1[N,128], s0[N,20], el1[N], er1[N]
//   colsum:   colsum0[c] = sum_n exp(s0[n][c] + b0[c])
//   deg/scan/scatter: build CSR of edges grouped by dst
//   gather1:  per-dst warp: softmax over incoming edges + weighted feature sum
//   gemm2:    h = elu(agg1+b1); [N,128]@[128,24] -> xl2, el2, er2
//   gather2:  layer-2 gather + fused final dual-softmax -> out
// ---------------------------------------------------------------------------

#define NN   50000
#define EE   500000
#define KDIM 512
#define HID  128
#define DOUT 20
#define NB_SCAN 98            // ceil(NN/512)

// ------------------------- device scratch ---------------------------------
__device__ __align__(16) float g_Wt1[KDIM * 160];   // fused B matrix, [k][c]
__device__ __align__(16) float g_Wt2[HID * 24];     // layer-2 B, [k][c]
__device__ __align__(16) float g_xl1[NN * HID];
__device__ __align__(16) float g_agg1[NN * HID];
__device__ __align__(16) float g_s0[NN * DOUT];
__device__ float g_el1[NN], g_er1[NN];
__device__ __align__(16) float g_xl2[NN * DOUT];
__device__ float g_el2[NN], g_er2[NN];
__device__ float g_colsum0[DOUT];
__device__ int g_is64;
// CSR
__device__ int g_deg[NN];
__device__ int g_rowoff[NN + 1];
__device__ int g_cursor[NN];
__device__ int g_bsum[NB_SCAN];
__device__ int g_boff[NB_SCAN];
__device__ int g_csrc[EE];

// ------------------------- helpers ----------------------------------------
__device__ __forceinline__ unsigned long long pack2(float x) {
    unsigned long long r;
    asm("mov.b64 %0, {%1, %2};" : "=l"(r) : "f"(x), "f"(x));
    return r;
}
__device__ __forceinline__ void ffma2(unsigned long long& c,
                                      unsigned long long a,
                                      unsigned long long b) {
    asm("fma.rn.f32x2 %0, %1, %2, %0;" : "+l"(c) : "l"(a), "l"(b));
}
__device__ __forceinline__ float2 unpack2(unsigned long long v) {
    float2 f;
    asm("mov.b64 {%0, %1}, %2;" : "=f"(f.x), "=f"(f.y) : "l"(v));
    return f;
}
__device__ __forceinline__ float eluf(float x) {
    return x > 0.f ? x : expm1f(x);
}
__device__ __forceinline__ float leaky(float x) {
    return x > 0.f ? x : 0.2f * x;
}

// ------------------------- dtype detection ---------------------------------
// int32 buffer read as int64 fuses pairs -> values >= 2^32 almost surely.
__global__ void detect_kernel(const void* ei) {
    if (threadIdx.x == 0) {
        const long long* p = (const long long*)ei;
        int ok64 = 1;
        for (int i = 0; i < 64; i++) {
            long long v = p[i];
            if (v < 0 || v >= NN) { ok64 = 0; break; }
        }
        g_is64 = ok64;
    }
}

__device__ __forceinline__ int edge_at(const void* ei, int idx) {
    if (g_is64) return (int)((const long long*)ei)[idx];
    return ((const int*)ei)[idx];
}

// ------------------------- prep -------------------------------------------
// grid 161 x 512 threads
__global__ void prep_kernel(const float* __restrict__ W0,
                            const float* __restrict__ Wl1, const float* __restrict__ Wr1,
                            const float* __restrict__ al1, const float* __restrict__ ar1,
                            const float* __restrict__ Wl2, const float* __restrict__ Wr2,
                            const float* __restrict__ al2, const float* __restrict__ ar2) {
    int b = blockIdx.x;
    int t = threadIdx.x;  // 0..511
    int flat = b * 512 + t;
    if (flat < NN) g_deg[flat] = 0;

    if (b < 128) {                       // Wl1^T column
        g_Wt1[t * 160 + b] = Wl1[b * KDIM + t];
    } else if (b < 148) {                // W0^T column
        g_Wt1[t * 160 + b] = W0[(b - 128) * KDIM + t];
    } else if (b == 148) {               // vl1 = Wl1^T @ al1
        float s = 0.f;
        for (int h = 0; h < HID; h++) s += Wl1[h * KDIM + t] * al1[h];
        g_Wt1[t * 160 + 148] = s;
    } else if (b == 149) {               // vr1 = Wr1^T @ ar1
        float s = 0.f;
        for (int h = 0; h < HID; h++) s += Wr1[h * KDIM + t] * ar1[h];
        g_Wt1[t * 160 + 149] = s;
    } else if (b < 160) {                // pad columns
        g_Wt1[t * 160 + b] = 0.f;
    } else {                             // b == 160: layer-2 weights + colsum zero
        if (t < HID) {
            for (int c = 0; c < DOUT; c++) g_Wt2[t * 24 + c] = Wl2[c * HID + t];
            float s = 0.f;
            for (int h = 0; h < DOUT; h++) s += Wl2[h * HID + t] * al2[h];
            g_Wt2[t * 24 + 20] = s;
            s = 0.f;
            for (int h = 0; h < DOUT; h++) s += Wr2[h * HID + t] * ar2[h];
            g_Wt2[t * 24 + 21] = s;
            g_Wt2[t * 24 + 22] = 0.f;
            g_Wt2[t * 24 + 23] = 0.f;
        } else if (t < 128 + DOUT) {
            g_colsum0[t - 128] = 0.f;
        }
    }
}

// ------------------------- fused big GEMM ---------------------------------
// C[N,160] = x[N,512] @ g_Wt1[512,160], f32x2 packed FMA.
// BM=128, BN=160, BK=32, 256 threads, micro-tile 8 rows x 10 cols (5 pairs).
__global__ __launch_bounds__(256) void gemm_big(const float* __restrict__ x) {
    __shared__ __align__(16) float As[32][132];  // [k][row], padded
    __shared__ __align__(16) float Bs[32][160];  // [k][col]
    int tid = threadIdx.x;
    int rt = tid >> 4;   // 0..15  (8 rows each)
    int ct = tid & 15;   // 0..15  (cols ct*4, 64+ct*4, 128+ct*2)
    int rowBase = blockIdx.x * 128;

    unsigned long long c2[8][5];
#pragma unroll
    for (int i = 0; i < 8; i++)
#pragma unroll
        for (int j = 0; j < 5; j++) c2[i][j] = 0ull;

    for (int k0 = 0; k0 < KDIM; k0 += 32) {
        __syncthreads();
        // load x tile (transposed into smem)
#pragma unroll
        for (int l = 0; l < 4; l++) {
            int idx = tid + l * 256;      // 0..1023
            int r = idx >> 3;             // 0..127
            int kc = idx & 7;             // 0..7 (float4 cols)
            int row = rowBase + r;
            float4 v = make_float4(0.f, 0.f, 0.f, 0.f);
            if (row < NN) v = *(const float4*)(x + row * KDIM + k0 + kc * 4);
            As[kc * 4 + 0][r] = v.x;
            As[kc * 4 + 1][r] = v.y;
            As[kc * 4 + 2][r] = v.z;
            As[kc * 4 + 3][r] = v.w;
        }
        // load W tile
#pragma unroll
        for (int l = 0; l < 5; l++) {
            int idx = tid + l * 256;      // 0..1279
            int r = idx / 40;
            int c4 = idx % 40;
            *(float4*)&Bs[r][c4 * 4] =
                *(const float4*)&g_Wt1[(k0 + r) * 160 + c4 * 4];
        }
        __syncthreads();

#pragma unroll 8
        for (int kk = 0; kk < 32; kk++) {
            float4 a0 = *(const float4*)&As[kk][rt * 8];
            float4 a1 = *(const float4*)&As[kk][rt * 8 + 4];
            double2 t0 = *(const double2*)&Bs[kk][ct * 4];
            double2 t1 = *(const double2*)&Bs[kk][64 + ct * 4];
            double  t2 = *(const double*)&Bs[kk][128 + ct * 2];
            unsigned long long bv0 = __double_as_longlong(t0.x);
            unsigned long long bv1 = __double_as_longlong(t0.y);
            unsigned long long bv2 = __double_as_longlong(t1.x);
            unsigned long long bv3 = __double_as_longlong(t1.y);
            unsigned long long bv4 = __double_as_longlong(t2);
            float av[8] = {a0.x, a0.y, a0.z, a0.w, a1.x, a1.y, a1.z, a1.w};
#pragma unroll
            for (int i = 0; i < 8; i++) {
                unsigned long long ap = pack2(av[i]);
                ffma2(c2[i][0], ap, bv0);
                ffma2(c2[i][1], ap, bv1);
                ffma2(c2[i][2], ap, bv2);
                ffma2(c2[i][3], ap, bv3);
                ffma2(c2[i][4], ap, bv4);
            }
        }
    }

#pragma unroll
    for (int i = 0; i < 8; i++) {
        int row = rowBase + rt * 8 + i;
        if (row < NN) {
            float2 p0 = unpack2(c2[i][0]), p1 = unpack2(c2[i][1]);
            float2 p2 = unpack2(c2[i][2]), p3 = unpack2(c2[i][3]);
            float2 p4 = unpack2(c2[i][4]);
            *(float4*)&g_xl1[row * HID + ct * 4] = make_float4(p0.x, p0.y, p1.x, p1.y);
            *(float4*)&g_xl1[row * HID + 64 + ct * 4] = make_float4(p2.x, p2.y, p3.x, p3.y);
            if (ct < 10) {
                *(float2*)&g_s0[row * DOUT + ct * 2] = make_float2(p4.x, p4.y);
            } else if (ct == 10) {
                g_el1[row] = p4.x;
                g_er1[row] = p4.y;
            }
        }
    }
}

// ------------------------- column-softmax reduce ---------------------------
__global__ void colsum_kernel(const float* __restrict__ b0) {
    __shared__ float bs[DOUT];
    int tid = threadIdx.x;
    if (tid < DOUT) bs[tid] = 0.f;
    __syncthreads();
    float ls[DOUT];
#pragma unroll
    for (int c = 0; c < DOUT; c++) ls[c] = 0.f;
    for (int n = blockIdx.x * blockDim.x + tid; n < NN; n += gridDim.x * blockDim.x) {
#pragma unroll
        for (int c = 0; c < DOUT; c++) ls[c] += expf(g_s0[n * DOUT + c] + b0[c]);
    }
#pragma unroll
    for (int c = 0; c < DOUT; c++) {
#pragma unroll
        for (int off = 16; off; off >>= 1)
            ls[c] += __shfl_xor_sync(0xffffffffu, ls[c], off);
    }
    if ((tid & 31) == 0) {
#pragma unroll
        for (int c = 0; c < DOUT; c++) atomicAdd(&bs[c], ls[c]);
    }
    __syncthreads();
    if (tid < DOUT) atomicAdd(&g_colsum0[tid], bs[tid]);
}

// ------------------------- CSR build ---------------------------------------
__global__ void deg_count(const void* __restrict__ ei) {
    int i = blockIdx.x * blockDim.x + threadIdx.x;
    if (i >= EE) return;
    int d = edge_at(ei, EE + i);
    atomicAdd(&g_deg[d], 1);
}

// per-block exclusive scan + block totals (512 threads, NB_SCAN blocks)
__global__ void scanA_kernel() {
    __shared__ int warpsum[16];
    int b = blockIdx.x, t = threadIdx.x;
    int i = b * 512 + t;
    int v = (i < NN) ? g_deg[i] : 0;
    int x = v;
#pragma unroll
    for (int off = 1; off < 32; off <<= 1) {
        int y = __shfl_up_sync(0xffffffffu, x, off);
        if ((t & 31) >= off) x += y;
    }
    if ((t & 31) == 31) warpsum[t >> 5] = x;
    __syncthreads();
    if (t < 16) {
        int s = warpsum[t];
#pragma unroll
        for (int off = 1; off < 16; off <<= 1) {
            int y = __shfl_up_sync(0xffffu, s, off);
            if (t >= off) s += y;
        }
        warpsum[t] = s;
    }
    __syncthreads();
    int incl = x + ((t >> 5) ? warpsum[(t >> 5) - 1] : 0);
    if (i < NN) g_rowoff[i] = incl - v;
    if (t == 511) g_bsum[b] = incl;
}

// scan block totals (1 block, 128 threads)
__global__ void scanB_kernel() {
    __shared__ int warpsum[4];
    int t = threadIdx.x;
    int v = (t < NB_SCAN) ? g_bsum[t] : 0;
    int x = v;
#pragma unroll
    for (int off = 1; off < 32; off <<= 1) {
        int y = __shfl_up_sync(0xffffffffu, x, off);
        if ((t & 31) >= off) x += y;
    }
    if ((t & 31) == 31) warpsum[t >> 5] = x;
    __syncthreads();
    if (t < 4) {
        int s = warpsum[t];
#pragma unroll
        for (int off = 1; off < 4; off <<= 1) {
            int y = __shfl_up_sync(0xfu, s, off);
            if (t >= off) s += y;
        }
        warpsum[t] = s;
    }
    __syncthreads();
    int incl = x + ((t >> 5) ? warpsum[(t >> 5) - 1] : 0);
    if (t < NB_SCAN) g_boff[t] = incl - v;
}

__global__ void scanC_kernel() {
    int b = blockIdx.x, t = threadIdx.x;
    int i = b * 512 + t;
    if (i < NN) {
        int o = g_rowoff[i] + g_boff[b];
        g_rowoff[i] = o;
        g_cursor[i] = o;
    }
    if (b == 0 && t == 0) g_rowoff[NN] = EE;
}

__global__ void scatter_kernel(const void* __restrict__ ei) {
    int i = blockIdx.x * blockDim.x + threadIdx.x;
    if (i >= EE) return;
    int s = edge_at(ei, i);
    int d = edge_at(ei, EE + i);
    int pos = atomicAdd(&g_cursor[d], 1);
    g_csrc[pos] = s;
}

// ------------------------- gather (layer 1) --------------------------------
// one warp per dst node, 8 warps/block
__global__ __launch_bounds__(256) void gather1_kernel() {
    int warp = (blockIdx.x * blockDim.x + threadIdx.x) >> 5;
    int lane = threadIdx.x & 31;
    if (warp >= NN) return;
    int dst = warp;
    int beg = g_rowoff[dst];
    int end = g_rowoff[dst + 1];
    float er = g_er1[dst];

    float denom = 0.f;
    for (int j = beg + lane; j < end; j += 32) {
        int s = g_csrc[j];
        denom += expf(leaky(g_el1[s] + er));
    }
#pragma unroll
    for (int off = 16; off; off >>= 1)
        denom += __shfl_xor_sync(0xffffffffu, denom, off);
    float inv = __fdividef(1.f, denom + 1e-16f);

    float4 acc = make_float4(0.f, 0.f, 0.f, 0.f);
    for (int j = beg; j < end; j++) {
        int s = g_csrc[j];
        float a = expf(leaky(g_el1[s] + er)) * inv;
        float4 v = *(const float4*)&g_xl1[s * HID + lane * 4];
        acc.x += a * v.x; acc.y += a * v.y; acc.z += a * v.z; acc.w += a * v.w;
    }
    *(float4*)&g_agg1[dst * HID + lane * 4] = acc;
}

// ------------------------- layer-2 GEMM ------------------------------------
// h = elu(agg1 + b1); C[N,24] = h @ g_Wt2[128,24]. 128 threads, micro 8x3.
__global__ __launch_bounds__(128) void gemm2_kernel(const float* __restrict__ b1) {
    __shared__ float Ws[HID * 24];
    __shared__ float Hs[128][33];
    int tid = threadIdx.x;
    for (int i = tid; i < HID * 24; i += 128) Ws[i] = g_Wt2[i];
    int rt = tid >> 3;  // 0..15 (8 rows each)
    int ct = tid & 7;   // 0..7  (3 cols each)
    int rowBase = blockIdx.x * 128;
    float acc[8][3] = {};

    for (int k0 = 0; k0 < HID; k0 += 32) {
        __syncthreads();
#pragma unroll
        for (int l = 0; l < 8; l++) {
            int idx = tid + l * 128;
            int r = idx >> 3;
            int kc = idx & 7;
            int row = rowBase + r;
            float4 v = make_float4(0.f, 0.f, 0.f, 0.f);
            if (row < NN) v = *(const float4*)&g_agg1[row * HID + k0 + kc * 4];
            int kb = k0 + kc * 4;
            Hs[r][kc * 4 + 0] = eluf(v.x + b1[kb + 0]);
            Hs[r][kc * 4 + 1] = eluf(v.y + b1[kb + 1]);
            Hs[r][kc * 4 + 2] = eluf(v.z + b1[kb + 2]);
            Hs[r][kc * 4 + 3] = eluf(v.w + b1[kb + 3]);
        }
        __syncthreads();
#pragma unroll
        for (int kk = 0; kk < 32; kk++) {
            float w0 = Ws[(k0 + kk) * 24 + ct * 3 + 0];
            float w1 = Ws[(k0 + kk) * 24 + ct * 3 + 1];
            float w2 = Ws[(k0 + kk) * 24 + ct * 3 + 2];
#pragma unroll
            for (int i = 0; i < 8; i++) {
                float a = Hs[rt * 8 + i][kk];
                acc[i][0] += a * w0;
                acc[i][1] += a * w1;
                acc[i][2] += a * w2;
            }
        }
    }
#pragma unroll
    for (int i = 0; i < 8; i++) {
        int row = rowBase + rt * 8 + i;
        if (row < NN) {
#pragma unroll
            for (int j = 0; j < 3; j++) {
                int c = ct * 3 + j;
                float vv = acc[i][j];
                if (c < DOUT) {
                    g_xl2[row * DOUT + c] = vv;
                } else if (c == 20) {
                    g_el2[row] = vv;
                } else if (c == 21) {
                    g_er2[row] = vv;
                }
            }
        }
    }
}

// ------------------------- gather (layer 2) + final combine ----------------
// one warp per dst node; lanes 0..19 hold the 20 output columns
__global__ __launch_bounds__(256) void gather2_kernel(const float* __restrict__ b0,
                                                      const float* __restrict__ b2,
                                                      float* __restrict__ out) {
    int warp = (blockIdx.x * blockDim.x + threadIdx.x) >> 5;
    int lane = threadIdx.x & 31;
    if (warp >= NN) return;
    int dst = warp;
    int beg = g_rowoff[dst];
    int end = g_rowoff[dst + 1];
    float er = g_er2[dst];

    float denom = 0.f;
    for (int j = beg + lane; j < end; j += 32) {
        int s = g_csrc[j];
        denom += expf(leaky(g_el2[s] + er));
    }
#pragma unroll
    for (int off = 16; off; off >>= 1)
        denom += __shfl_xor_sync(0xffffffffu, denom, off);
    float inv = __fdividef(1.f, denom + 1e-16f);

    float acc = 0.f;
    for (int j = beg; j < end; j++) {
        int s = g_csrc[j];
        float a = expf(leaky(g_el2[s] + er)) * inv;
        if (lane < DOUT) acc += a * g_xl2[s * DOUT + lane];
    }
    // row softmax over 20 lanes + dual-softmax combine
    float ev = 0.f;
    if (lane < DOUT) ev = expf(acc + b2[lane]);
    float rs = ev;
#pragma unroll
    for (int off = 16; off; off >>= 1)
        rs += __shfl_xor_sync(0xffffffffu, rs, off);
    float ir = __fdividef(1.f, rs);
    if (lane < DOUT) {
        float p0 = expf(g_s0[dst * DOUT + lane] + b0[lane]) *
                   __fdividef(1.f, g_colsum0[lane]);
        out[dst * DOUT + lane] = p0 * ev * ir;
    }
}

// ------------------------- launch ------------------------------------------
extern "C" void kernel_launch(void* const* d_in, const int* in_sizes, int n_in,
                              void* d_out, int out_size) {
    const float* x        = (const float*)d_in[0];
    const void* ei        = d_in[1];
    const float* W0       = (const float*)d_in[2];
    const float* b0       = (const float*)d_in[3];
    const float* g1Wl     = (const float*)d_in[4];
    const float* g1Wr     = (const float*)d_in[5];
    const float* g1al     = (const float*)d_in[6];
    const float* g1ar     = (const float*)d_in[7];
    const float* g1b      = (const float*)d_in[8];
    const float* g2Wl     = (const float*)d_in[9];
    const float* g2Wr     = (const float*)d_in[10];
    const float* g2al     = (const float*)d_in[11];
    const float* g2ar     = (const float*)d_in[12];
    const float* g2b      = (const float*)d_in[13];
    float* out            = (float*)d_out;

    detect_kernel<<<1, 32>>>(ei);
    prep_kernel<<<161, 512>>>(W0, g1Wl, g1Wr, g1al, g1ar, g2Wl, g2Wr, g2al, g2ar);
    gemm_big<<<(NN + 127) / 128, 256>>>(x);
    colsum_kernel<<<128, 256>>>(b0);
    deg_count<<<(EE + 255) / 256, 256>>>(ei);
    scanA_kernel<<<NB_SCAN, 512>>>();
    scanB_kernel<<<1, 128>>>();
    scanC_kernel<<<NB_SCAN, 512>>>();
    scatter_kernel<<<(EE + 255) / 256, 256>>>(ei);
    gather1_kernel<<<(NN * 32 + 255) / 256, 256>>>();
    gemm2_kernel<<<(NN + 127) / 128, 128>>>(g1b);
    gather2_kernel<<<(NN * 32 + 255) / 256, 256>>>(b0, g2b, out);
}

// round 5
// speedup vs baseline: 1.3583x; 1.3583x over previous
#include <cuda_runtime.h>
#include <cuda_bf16.h>
#include <math.h>
#include <stdint.h>

// ---------------------------------------------------------------------------
// GAT pipeline. Big GEMM on warp-level mma.sync (bf16 split-precision, fp32
// accumulate) since the harness PTX target is sm_103 (no 'a': tcgen05 illegal).
//   detect:   edge_index dtype sniff (JAX x64-disabled -> int32 silently)
//   prep:     fused fp32 weight matrix Wt1[512][160] + attention vectors
//   prep2:    Wt1 -> bf16 hi/lo in mma-fragment order
//   gemm_mma: [N,512]x[512,160]: xl1[N,128], s0[N,20], el1, er1
//   colsum:   colsum0[c] = sum_n exp(s0[n][c] + b0[c])
//   deg/scan/scatter: build CSR of edges grouped by dst
//   gather1:  per-dst warp: edge softmax + weighted feature sum (atomic-free)
//   gemm2:    h = elu(agg1+b1); [N,128]@[128,24] -> xl2, el2, er2
//   gather2:  layer-2 gather + fused final dual-softmax -> out
// ---------------------------------------------------------------------------

#define NN   50000
#define EE   500000
#define KDIM 512
#define HID  128
#define DOUT 20
#define NB_SCAN 98            // ceil(NN/512)

#define NSTEPS 32             // 512 / 16 k-steps
#define NTILES 20             // 160 / 8 n-tiles
// B fragment array: [step][tile][lane] -> uint2 (4 bf16)
#define BFRAG_CNT (NSTEPS * NTILES * 32)
// smem chunk = 8 k-steps of both hi and lo fragment tables
#define CH_STEPS 8
#define CH_HALF (CH_STEPS * NTILES * 32 * 8)      // 40960 bytes
#define SMEM_SZ (2 * CH_HALF)                     // 81920 bytes

// ------------------------- device scratch ---------------------------------
__device__ __align__(16) float g_Wt1[KDIM * 160];   // fused B matrix, [k][c]
__device__ __align__(16) float g_Wt2[HID * 24];     // layer-2 B, [k][c]
__device__ __align__(16) uint2 g_Bfh[BFRAG_CNT];    // B hi fragments
__device__ __align__(16) uint2 g_Bfl[BFRAG_CNT];    // B lo fragments
__device__ __align__(16) float g_xl1[NN * HID];
__device__ __align__(16) float g_agg1[NN * HID];
__device__ __align__(16) float g_s0[NN * DOUT];
__device__ float g_el1[NN], g_er1[NN];
__device__ __align__(16) float g_xl2[NN * DOUT];
__device__ float g_el2[NN], g_er2[NN];
__device__ float g_colsum0[DOUT];
__device__ int g_is64;
// CSR
__device__ int g_deg[NN];
__device__ int g_rowoff[NN + 1];
__device__ int g_cursor[NN];
__device__ int g_bsum[NB_SCAN];
__device__ int g_boff[NB_SCAN];
__device__ int g_csrc[EE];

// ------------------------- helpers ----------------------------------------
__device__ __forceinline__ float eluf(float x) {
    return x > 0.f ? x : expm1f(x);
}
__device__ __forceinline__ float leaky(float x) {
    return x > 0.f ? x : 0.2f * x;
}
// pack two floats to bf16x2 (lo half = a, hi half = b)
__device__ __forceinline__ uint32_t packbf(float a, float b) {
    uint32_t r;
    asm("cvt.rn.bf16x2.f32 %0, %1, %2;" : "=r"(r) : "f"(b), "f"(a));
    return r;
}
__device__ __forceinline__ float bflo(float v) {
    __nv_bfloat16 h = __float2bfloat16(v);
    return v - __bfloat162float(h);
}
__device__ __forceinline__ void mma_bf16(float& c0, float& c1, float& c2, float& c3,
                                         uint32_t a0, uint32_t a1, uint32_t a2, uint32_t a3,
                                         uint32_t b0, uint32_t b1) {
    asm volatile(
        "mma.sync.aligned.m16n8k16.row.col.f32.bf16.bf16.f32 "
        "{%0,%1,%2,%3}, {%4,%5,%6,%7}, {%8,%9}, {%0,%1,%2,%3};"
        : "+f"(c0), "+f"(c1), "+f"(c2), "+f"(c3)
        : "r"(a0), "r"(a1), "r"(a2), "r"(a3), "r"(b0), "r"(b1));
}

// ------------------------- dtype detection ---------------------------------
__global__ void detect_kernel(const void* ei) {
    if (threadIdx.x == 0) {
        const long long* p = (const long long*)ei;
        int ok64 = 1;
        for (int i = 0; i < 64; i++) {
            long long v = p[i];
            if (v < 0 || v >= NN) { ok64 = 0; break; }
        }
        g_is64 = ok64;
    }
}
__device__ __forceinline__ int edge_at(const void* ei, int idx) {
    if (g_is64) return (int)((const long long*)ei)[idx];
    return ((const int*)ei)[idx];
}

// ------------------------- prep -------------------------------------------
__global__ void prep_kernel(const float* __restrict__ W0,
                            const float* __restrict__ Wl1, const float* __restrict__ Wr1,
                            const float* __restrict__ al1, const float* __restrict__ ar1,
                            const float* __restrict__ Wl2, const float* __restrict__ Wr2,
                            const float* __restrict__ al2, const float* __restrict__ ar2) {
    int b = blockIdx.x;
    int t = threadIdx.x;  // 0..511
    int flat = b * 512 + t;
    if (flat < NN) g_deg[flat] = 0;

    if (b < 128) {
        g_Wt1[t * 160 + b] = Wl1[b * KDIM + t];
    } else if (b < 148) {
        g_Wt1[t * 160 + b] = W0[(b - 128) * KDIM + t];
    } else if (b == 148) {
        float s = 0.f;
        for (int h = 0; h < HID; h++) s += Wl1[h * KDIM + t] * al1[h];
        g_Wt1[t * 160 + 148] = s;
    } else if (b == 149) {
        float s = 0.f;
        for (int h = 0; h < HID; h++) s += Wr1[h * KDIM + t] * ar1[h];
        g_Wt1[t * 160 + 149] = s;
    } else if (b < 160) {
        g_Wt1[t * 160 + b] = 0.f;
    } else {
        if (t < HID) {
            for (int c = 0; c < DOUT; c++) g_Wt2[t * 24 + c] = Wl2[c * HID + t];
            float s = 0.f;
            for (int h = 0; h < DOUT; h++) s += Wl2[h * HID + t] * al2[h];
            g_Wt2[t * 24 + 20] = s;
            s = 0.f;
            for (int h = 0; h < DOUT; h++) s += Wr2[h * HID + t] * ar2[h];
            g_Wt2[t * 24 + 21] = s;
            g_Wt2[t * 24 + 22] = 0.f;
            g_Wt2[t * 24 + 23] = 0.f;
        } else if (t < 128 + DOUT) {
            g_colsum0[t - 128] = 0.f;
        }
    }
}

// Wt1 fp32 -> bf16 hi/lo fragments for mma.sync m16n8k16 (B col-major k x n):
// frag idx f = (s*NTILES + t)*32 + lane; lane g=lane>>2, q=lane&3.
// reg0 = {B[16s+2q][8t+g], B[16s+2q+1][8t+g]}, reg1 = same with k+8.
__global__ void prep2_kernel() {
    int idx = blockIdx.x * blockDim.x + threadIdx.x;
    if (idx >= BFRAG_CNT) return;
    int lane = idx & 31;
    int t = (idx >> 5) % NTILES;
    int s = idx / (NTILES * 32);
    int g = lane >> 2, q = lane & 3;
    int n = t * 8 + g;
    int k = s * 16 + 2 * q;
    float v0 = g_Wt1[k * 160 + n];
    float v1 = g_Wt1[(k + 1) * 160 + n];
    float v2 = g_Wt1[(k + 8) * 160 + n];
    float v3 = g_Wt1[(k + 9) * 160 + n];
    g_Bfh[idx] = make_uint2(packbf(v0, v1), packbf(v2, v3));
    g_Bfl[idx] = make_uint2(packbf(bflo(v0), bflo(v1)), packbf(bflo(v2), bflo(v3)));
}

// ------------------------- mma.sync big GEMM -------------------------------
// 512 threads = 16 warps (4 mw x 4 nw). BM=128, BN=160. Warp tile 32x40.
// Split precision: D += Ah*Bh + Ah*Bl + Al*Bh (fp32 acc).
__global__ __launch_bounds__(512, 1) void gemm_mma(const float* __restrict__ x) {
    extern __shared__ __align__(16) char smB[];   // [hi: CH_HALF][lo: CH_HALF]
    int tid = threadIdx.x;
    int wid = tid >> 5;
    int lane = tid & 31;
    int mw = wid >> 2;          // 0..3
    int nw = wid & 3;           // 0..3
    int g = lane >> 2, q = lane & 3;
    int rowBase = blockIdx.x * 128;

    // rows this lane touches (2 m16 tiles: mt=0 rows r0/r0+8, mt=1 rows +16/+24)
    int r0 = rowBase + mw * 32 + g;

    float acc[2][5][4];
#pragma unroll
    for (int i = 0; i < 2; i++)
#pragma unroll
        for (int j = 0; j < 5; j++)
#pragma unroll
            for (int k = 0; k < 4; k++) acc[i][j][k] = 0.f;

    const uint4* srcH = reinterpret_cast<const uint4*>(g_Bfh);
    const uint4* srcL = reinterpret_cast<const uint4*>(g_Bfl);
    uint4* smH = reinterpret_cast<uint4*>(smB);
    uint4* smL = reinterpret_cast<uint4*>(smB + CH_HALF);

    for (int ch = 0; ch < 4; ch++) {
        __syncthreads();
        // copy this K-chunk's B fragments (hi+lo) into smem: 2560 uint4 each
        {
            int base = ch * (CH_HALF / 16);
#pragma unroll
            for (int i = 0; i < 5; i++) {
                int s = tid + i * 512;
                smH[s] = srcH[base + s];
                smL[s] = srcL[base + s];
            }
        }
        __syncthreads();

#pragma unroll
        for (int s = 0; s < CH_STEPS; s++) {
            int k0 = ch * 128 + s * 16;
            // ---- A fragments straight from gmem (fragment layout) ----
            uint32_t ah[2][4], al[2][4];
#pragma unroll
            for (int mt = 0; mt < 2; mt++) {
                int ra = r0 + mt * 16;
                int rb = ra + 8;
                const float* pa = x + (size_t)ra * KDIM + k0 + 2 * q;
                const float* pb = x + (size_t)rb * KDIM + k0 + 2 * q;
                float2 va0 = (ra < NN) ? *(const float2*)pa : make_float2(0.f, 0.f);
                float2 va1 = (ra < NN) ? *(const float2*)(pa + 8) : make_float2(0.f, 0.f);
                float2 vb0 = (rb < NN) ? *(const float2*)pb : make_float2(0.f, 0.f);
                float2 vb1 = (rb < NN) ? *(const float2*)(pb + 8) : make_float2(0.f, 0.f);
                ah[mt][0] = packbf(va0.x, va0.y);
                ah[mt][1] = packbf(vb0.x, vb0.y);
                ah[mt][2] = packbf(va1.x, va1.y);
                ah[mt][3] = packbf(vb1.x, vb1.y);
                al[mt][0] = packbf(bflo(va0.x), bflo(va0.y));
                al[mt][1] = packbf(bflo(vb0.x), bflo(vb0.y));
                al[mt][2] = packbf(bflo(va1.x), bflo(va1.y));
                al[mt][3] = packbf(bflo(vb1.x), bflo(vb1.y));
            }
            // ---- B fragments from smem, 5 n-tiles for this warp ----
            int sbase = (s * NTILES + nw * 5) * 32 + lane;
#pragma unroll
            for (int nt = 0; nt < 5; nt++) {
                uint2 bh = *(uint2*)(smB + (size_t)(sbase + nt * 32) * 8);
                uint2 bl = *(uint2*)(smB + CH_HALF + (size_t)(sbase + nt * 32) * 8);
#pragma unroll
                for (int mt = 0; mt < 2; mt++) {
                    mma_bf16(acc[mt][nt][0], acc[mt][nt][1], acc[mt][nt][2], acc[mt][nt][3],
                             ah[mt][0], ah[mt][1], ah[mt][2], ah[mt][3], bh.x, bh.y);
                    mma_bf16(acc[mt][nt][0], acc[mt][nt][1], acc[mt][nt][2], acc[mt][nt][3],
                             ah[mt][0], ah[mt][1], ah[mt][2], ah[mt][3], bl.x, bl.y);
                    mma_bf16(acc[mt][nt][0], acc[mt][nt][1], acc[mt][nt][2], acc[mt][nt][3],
                             al[mt][0], al[mt][1], al[mt][2], al[mt][3], bh.x, bh.y);
                }
            }
        }
    }

    // ---- epilogue ----
#pragma unroll
    for (int mt = 0; mt < 2; mt++) {
#pragma unroll
        for (int half = 0; half < 2; half++) {
            int row = r0 + mt * 16 + half * 8;
            if (row >= NN) continue;
#pragma unroll
            for (int nt = 0; nt < 5; nt++) {
                int col = nw * 40 + nt * 8 + 2 * q;
                float c0 = acc[mt][nt][half * 2 + 0];
                float c1 = acc[mt][nt][half * 2 + 1];
                if (col < HID) {
                    *(float2*)&g_xl1[(size_t)row * HID + col] = make_float2(c0, c1);
                } else {
                    int cc = col - HID;
                    if (cc < DOUT) {
                        *(float2*)&g_s0[(size_t)row * DOUT + cc] = make_float2(c0, c1);
                    } else if (cc == DOUT) {
                        g_el1[row] = c0;
                        g_er1[row] = c1;
                    }
                }
            }
        }
    }
}

// ------------------------- column-softmax reduce ---------------------------
__global__ void colsum_kernel(const float* __restrict__ b0) {
    __shared__ float bs[DOUT];
    int tid = threadIdx.x;
    if (tid < DOUT) bs[tid] = 0.f;
    __syncthreads();
    float ls[DOUT];
#pragma unroll
    for (int c = 0; c < DOUT; c++) ls[c] = 0.f;
    for (int n = blockIdx.x * blockDim.x + tid; n < NN; n += gridDim.x * blockDim.x) {
#pragma unroll
        for (int c = 0; c < DOUT; c++) ls[c] += expf(g_s0[n * DOUT + c] + b0[c]);
    }
#pragma unroll
    for (int c = 0; c < DOUT; c++) {
#pragma unroll
        for (int off = 16; off; off >>= 1)
            ls[c] += __shfl_xor_sync(0xffffffffu, ls[c], off);
    }
    if ((tid & 31) == 0) {
#pragma unroll
        for (int c = 0; c < DOUT; c++) atomicAdd(&bs[c], ls[c]);
    }
    __syncthreads();
    if (tid < DOUT) atomicAdd(&g_colsum0[tid], bs[tid]);
}

// ------------------------- CSR build ---------------------------------------
__global__ void deg_count(const void* __restrict__ ei) {
    int i = blockIdx.x * blockDim.x + threadIdx.x;
    if (i >= EE) return;
    int d = edge_at(ei, EE + i);
    atomicAdd(&g_deg[d], 1);
}

__global__ void scanA_kernel() {
    __shared__ int warpsum[16];
    int b = blockIdx.x, t = threadIdx.x;
    int i = b * 512 + t;
    int v = (i < NN) ? g_deg[i] : 0;
    int x = v;
#pragma unroll
    for (int off = 1; off < 32; off <<= 1) {
        int y = __shfl_up_sync(0xffffffffu, x, off);
        if ((t & 31) >= off) x += y;
    }
    if ((t & 31) == 31) warpsum[t >> 5] = x;
    __syncthreads();
    if (t < 16) {
        int s = warpsum[t];
#pragma unroll
        for (int off = 1; off < 16; off <<= 1) {
            int y = __shfl_up_sync(0xffffu, s, off);
            if (t >= off) s += y;
        }
        warpsum[t] = s;
    }
    __syncthreads();
    int incl = x + ((t >> 5) ? warpsum[(t >> 5) - 1] : 0);
    if (i < NN) g_rowoff[i] = incl - v;
    if (t == 511) g_bsum[b] = incl;
}

__global__ void scanB_kernel() {
    __shared__ int warpsum[4];
    int t = threadIdx.x;
    int v = (t < NB_SCAN) ? g_bsum[t] : 0;
    int x = v;
#pragma unroll
    for (int off = 1; off < 32; off <<= 1) {
        int y = __shfl_up_sync(0xffffffffu, x, off);
        if ((t & 31) >= off) x += y;
    }
    if ((t & 31) == 31) warpsum[t >> 5] = x;
    __syncthreads();
    if (t < 4) {
        int s = warpsum[t];
#pragma unroll
        for (int off = 1; off < 4; off <<= 1) {
            int y = __shfl_up_sync(0xfu, s, off);
            if (t >= off) s += y;
        }
        warpsum[t] = s;
    }
    __syncthreads();
    int incl = x + ((t >> 5) ? warpsum[(t >> 5) - 1] : 0);
    if (t < NB_SCAN) g_boff[t] = incl - v;
}

__global__ void scanC_kernel() {
    int b = blockIdx.x, t = threadIdx.x;
    int i = b * 512 + t;
    if (i < NN) {
        int o = g_rowoff[i] + g_boff[b];
        g_rowoff[i] = o;
        g_cursor[i] = o;
    }
    if (b == 0 && t == 0) g_rowoff[NN] = EE;
}

__global__ void scatter_kernel(const void* __restrict__ ei) {
    int i = blockIdx.x * blockDim.x + threadIdx.x;
    if (i >= EE) return;
    int s = edge_at(ei, i);
    int d = edge_at(ei, EE + i);
    int pos = atomicAdd(&g_cursor[d], 1);
    g_csrc[pos] = s;
}

// ------------------------- gather (layer 1) --------------------------------
__global__ __launch_bounds__(256) void gather1_kernel() {
    int warp = (blockIdx.x * blockDim.x + threadIdx.x) >> 5;
    int lane = threadIdx.x & 31;
    if (warp >= NN) return;
    int dst = warp;
    int beg = g_rowoff[dst];
    int end = g_rowoff[dst + 1];
    float er = g_er1[dst];

    float denom = 0.f;
    for (int j = beg + lane; j < end; j += 32) {
        int s = g_csrc[j];
        denom += expf(leaky(g_el1[s] + er));
    }
#pragma unroll
    for (int off = 16; off; off >>= 1)
        denom += __shfl_xor_sync(0xffffffffu, denom, off);
    float inv = __fdividef(1.f, denom + 1e-16f);

    float4 acc = make_float4(0.f, 0.f, 0.f, 0.f);
    for (int j = beg; j < end; j++) {
        int s = g_csrc[j];
        float a = expf(leaky(g_el1[s] + er)) * inv;
        float4 v = *(const float4*)&g_xl1[(size_t)s * HID + lane * 4];
        acc.x += a * v.x; acc.y += a * v.y; acc.z += a * v.z; acc.w += a * v.w;
    }
    *(float4*)&g_agg1[(size_t)dst * HID + lane * 4] = acc;
}

// ------------------------- layer-2 GEMM ------------------------------------
__global__ __launch_bounds__(128) void gemm2_kernel(const float* __restrict__ b1) {
    __shared__ float Ws[HID * 24];
    __shared__ float Hs[128][33];
    int tid = threadIdx.x;
    for (int i = tid; i < HID * 24; i += 128) Ws[i] = g_Wt2[i];
    int rt = tid >> 3;
    int ct = tid & 7;
    int rowBase = blockIdx.x * 128;
    float acc[8][3] = {};

    for (int k0 = 0; k0 < HID; k0 += 32) {
        __syncthreads();
#pragma unroll
        for (int l = 0; l < 8; l++) {
            int idx = tid + l * 128;
            int r = idx >> 3;
            int kc = idx & 7;
            int row = rowBase + r;
            float4 v = make_float4(0.f, 0.f, 0.f, 0.f);
            if (row < NN) v = *(const float4*)&g_agg1[(size_t)row * HID + k0 + kc * 4];
            int kb = k0 + kc * 4;
            Hs[r][kc * 4 + 0] = eluf(v.x + b1[kb + 0]);
            Hs[r][kc * 4 + 1] = eluf(v.y + b1[kb + 1]);
            Hs[r][kc * 4 + 2] = eluf(v.z + b1[kb + 2]);
            Hs[r][kc * 4 + 3] = eluf(v.w + b1[kb + 3]);
        }
        __syncthreads();
#pragma unroll
        for (int kk = 0; kk < 32; kk++) {
            float w0 = Ws[(k0 + kk) * 24 + ct * 3 + 0];
            float w1 = Ws[(k0 + kk) * 24 + ct * 3 + 1];
            float w2 = Ws[(k0 + kk) * 24 + ct * 3 + 2];
#pragma unroll
            for (int i = 0; i < 8; i++) {
                float a = Hs[rt * 8 + i][kk];
                acc[i][0] += a * w0;
                acc[i][1] += a * w1;
                acc[i][2] += a * w2;
            }
        }
    }
#pragma unroll
    for (int i = 0; i < 8; i++) {
        int row = rowBase + rt * 8 + i;
        if (row < NN) {
#pragma unroll
            for (int j = 0; j < 3; j++) {
                int c = ct * 3 + j;
                float vv = acc[i][j];
                if (c < DOUT) {
                    g_xl2[row * DOUT + c] = vv;
                } else if (c == 20) {
                    g_el2[row] = vv;
                } else if (c == 21) {
                    g_er2[row] = vv;
                }
            }
        }
    }
}

// ------------------------- gather (layer 2) + final combine ----------------
__global__ __launch_bounds__(256) void gather2_kernel(const float* __restrict__ b0,
                                                      const float* __restrict__ b2,
                                                      float* __restrict__ out) {
    int warp = (blockIdx.x * blockDim.x + threadIdx.x) >> 5;
    int lane = threadIdx.x & 31;
    if (warp >= NN) return;
    int dst = warp;
    int beg = g_rowoff[dst];
    int end = g_rowoff[dst + 1];
    float er = g_er2[dst];

    float denom = 0.f;
    for (int j = beg + lane; j < end; j += 32) {
        int s = g_csrc[j];
        denom += expf(leaky(g_el2[s] + er));
    }
#pragma unroll
    for (int off = 16; off; off >>= 1)
        denom += __shfl_xor_sync(0xffffffffu, denom, off);
    float inv = __fdividef(1.f, denom + 1e-16f);

    float acc = 0.f;
    for (int j = beg; j < end; j++) {
        int s = g_csrc[j];
        float a = expf(leaky(g_el2[s] + er)) * inv;
        if (lane < DOUT) acc += a * g_xl2[s * DOUT + lane];
    }
    float ev = 0.f;
    if (lane < DOUT) ev = expf(acc + b2[lane]);
    float rs = ev;
#pragma unroll
    for (int off = 16; off; off >>= 1)
        rs += __shfl_xor_sync(0xffffffffu, rs, off);
    float ir = __fdividef(1.f, rs);
    if (lane < DOUT) {
        float p0 = expf(g_s0[dst * DOUT + lane] + b0[lane]) *
                   __fdividef(1.f, g_colsum0[lane]);
        out[dst * DOUT + lane] = p0 * ev * ir;
    }
}

// ------------------------- launch ------------------------------------------
extern "C" void kernel_launch(void* const* d_in, const int* in_sizes, int n_in,
                              void* d_out, int out_size) {
    const float* x        = (const float*)d_in[0];
    const void* ei        = d_in[1];
    const float* W0       = (const float*)d_in[2];
    const float* b0       = (const float*)d_in[3];
    const float* g1Wl     = (const float*)d_in[4];
    const float* g1Wr     = (const float*)d_in[5];
    const float* g1al     = (const float*)d_in[6];
    const float* g1ar     = (const float*)d_in[7];
    const float* g1b      = (const float*)d_in[8];
    const float* g2Wl     = (const float*)d_in[9];
    const float* g2Wr     = (const float*)d_in[10];
    const float* g2al     = (const float*)d_in[11];
    const float* g2ar     = (const float*)d_in[12];
    const float* g2b      = (const float*)d_in[13];
    float* out            = (float*)d_out;

    cudaFuncSetAttribute(gemm_mma, cudaFuncAttributeMaxDynamicSharedMemorySize, SMEM_SZ);

    detect_kernel<<<1, 32>>>(ei);
    prep_kernel<<<161, 512>>>(W0, g1Wl, g1Wr, g1al, g1ar, g2Wl, g2Wr, g2al, g2ar);
    prep2_kernel<<<(BFRAG_CNT + 255) / 256, 256>>>();
    gemm_mma<<<(NN + 127) / 128, 512, SMEM_SZ>>>(x);
    colsum_kernel<<<400, 256>>>(b0);
    deg_count<<<(EE + 255) / 256, 256>>>(ei);
    scanA_kernel<<<NB_SCAN, 512>>>();
    scanB_kernel<<<1, 128>>>();
    scanC_kernel<<<NB_SCAN, 512>>>();
    scatter_kernel<<<(EE + 255) / 256, 256>>>(ei);
    gather1_kernel<<<(NN * 32 + 255) / 256, 256>>>();
    gemm2_kernel<<<(NN + 127) / 128, 128>>>(g1b);
    gather2_kernel<<<(NN * 32 + 255) / 256, 256>>>(b0, g2b, out);
}

// round 6
// speedup vs baseline: 1.7433x; 1.2835x over previous
#include <cuda_runtime.h>
#include <cuda_bf16.h>
#include <math.h>
#include <stdint.h>

// ---------------------------------------------------------------------------
// GAT pipeline. Big GEMM: warp-level mma.sync bf16 split-precision with
// smem-staged A/B fragment tables (A converted fp32->bf16 hi/lo on the fly).
//   detect:   edge_index dtype sniff (JAX x64-disabled -> int32 silently)
//   prep:     fused fp32 weight matrix Wt1[512][160] + attention vectors
//   prep2:    Wt1 -> bf16 hi/lo in mma-fragment order
//   gemm_mma: [N,512]x[512,160]: xl1[N,128], s0[N,20], el1, er1
//   colsum:   colsum0[c] = sum_n exp(s0[n][c] + b0[c])
//   deg/scan/scatter: build CSR of edges grouped by dst
//   gather1:  per-dst warp: edge softmax + weighted feature sum (atomic-free)
//   gemm2:    h = elu(agg1+b1); [N,128]@[128,24] -> xl2, el2, er2
//   gather2:  layer-2 gather + fused final dual-softmax -> out
// ---------------------------------------------------------------------------

#define NN   50000
#define EE   500000
#define KDIM 512
#define HID  128
#define DOUT 20
#define NB_SCAN 98            // ceil(NN/512)

#define NSTEPS 32             // 512 / 16 k-steps
#define NTILES 20             // 160 / 8 n-tiles
#define BFRAG_CNT (NSTEPS * NTILES * 32)   // B fragment table entries (uint2)

// gemm tiling: BM=64, BN=160, chunk K=64 (4 k-steps), 256 threads = 8 warps
#define CH_STEPS 4
#define NCHUNKS 8
// smem layout (bytes)
#define OFF_AF_H 0
#define OFF_AF_L 8192                     // 4s*4mt*32 lanes * 16B = 8192
#define OFF_B_H  16384
#define OFF_B_L  (OFF_B_H + 20480)        // 4s*20t*32 * 8B = 20480
#define SMEM_SZ  (OFF_B_L + 20480)        // 57344

// ------------------------- device scratch ---------------------------------
__device__ __align__(16) float g_Wt1[KDIM * 160];   // fused B matrix, [k][c]
__device__ __align__(16) float g_Wt2[HID * 24];     // layer-2 B, [k][c]
__device__ __align__(16) uint2 g_Bfh[BFRAG_CNT];    // B hi fragments
__device__ __align__(16) uint2 g_Bfl[BFRAG_CNT];    // B lo fragments
__device__ __align__(16) float g_xl1[NN * HID];
__device__ __align__(16) float g_agg1[NN * HID];
__device__ __align__(16) float g_s0[NN * DOUT];
__device__ float g_el1[NN], g_er1[NN];
__device__ __align__(16) float g_xl2[NN * DOUT];
__device__ float g_el2[NN], g_er2[NN];
__device__ float g_colsum0[DOUT];
__device__ int g_is64;
// CSR
__device__ int g_deg[NN];
__device__ int g_rowoff[NN + 1];
__device__ int g_cursor[NN];
__device__ int g_bsum[NB_SCAN];
__device__ int g_boff[NB_SCAN];
__device__ int g_csrc[EE];

// ------------------------- helpers ----------------------------------------
__device__ __forceinline__ float eluf(float x) {
    return x > 0.f ? x : expm1f(x);
}
__device__ __forceinline__ float leaky(float x) {
    return x > 0.f ? x : 0.2f * x;
}
// pack two floats to bf16x2 (lo half = a, hi half = b)
__device__ __forceinline__ uint32_t packbf(float a, float b) {
    uint32_t r;
    asm("cvt.rn.bf16x2.f32 %0, %1, %2;" : "=r"(r) : "f"(b), "f"(a));
    return r;
}
__device__ __forceinline__ float bflo(float v) {
    __nv_bfloat16 h = __float2bfloat16(v);
    return v - __bfloat162float(h);
}
__device__ __forceinline__ void mma_bf16(float& c0, float& c1, float& c2, float& c3,
                                         uint32_t a0, uint32_t a1, uint32_t a2, uint32_t a3,
                                         uint32_t b0, uint32_t b1) {
    asm volatile(
        "mma.sync.aligned.m16n8k16.row.col.f32.bf16.bf16.f32 "
        "{%0,%1,%2,%3}, {%4,%5,%6,%7}, {%8,%9}, {%0,%1,%2,%3};"
        : "+f"(c0), "+f"(c1), "+f"(c2), "+f"(c3)
        : "r"(a0), "r"(a1), "r"(a2), "r"(a3), "r"(b0), "r"(b1));
}

// ------------------------- dtype detection ---------------------------------
__global__ void detect_kernel(const void* ei) {
    if (threadIdx.x == 0) {
        const long long* p = (const long long*)ei;
        int ok64 = 1;
        for (int i = 0; i < 64; i++) {
            long long v = p[i];
            if (v < 0 || v >= NN) { ok64 = 0; break; }
        }
        g_is64 = ok64;
    }
}
__device__ __forceinline__ int edge_at(const void* ei, int idx) {
    if (g_is64) return (int)((const long long*)ei)[idx];
    return ((const int*)ei)[idx];
}

// ------------------------- prep -------------------------------------------
__global__ void prep_kernel(const float* __restrict__ W0,
                            const float* __restrict__ Wl1, const float* __restrict__ Wr1,
                            const float* __restrict__ al1, const float* __restrict__ ar1,
                            const float* __restrict__ Wl2, const float* __restrict__ Wr2,
                            const float* __restrict__ al2, const float* __restrict__ ar2) {
    int b = blockIdx.x;
    int t = threadIdx.x;  // 0..511
    int flat = b * 512 + t;
    if (flat < NN) g_deg[flat] = 0;

    if (b < 128) {
        g_Wt1[t * 160 + b] = Wl1[b * KDIM + t];
    } else if (b < 148) {
        g_Wt1[t * 160 + b] = W0[(b - 128) * KDIM + t];
    } else if (b == 148) {
        float s = 0.f;
        for (int h = 0; h < HID; h++) s += Wl1[h * KDIM + t] * al1[h];
        g_Wt1[t * 160 + 148] = s;
    } else if (b == 149) {
        float s = 0.f;
        for (int h = 0; h < HID; h++) s += Wr1[h * KDIM + t] * ar1[h];
        g_Wt1[t * 160 + 149] = s;
    } else if (b < 160) {
        g_Wt1[t * 160 + b] = 0.f;
    } else {
        if (t < HID) {
            for (int c = 0; c < DOUT; c++) g_Wt2[t * 24 + c] = Wl2[c * HID + t];
            float s = 0.f;
            for (int h = 0; h < DOUT; h++) s += Wl2[h * HID + t] * al2[h];
            g_Wt2[t * 24 + 20] = s;
            s = 0.f;
            for (int h = 0; h < DOUT; h++) s += Wr2[h * HID + t] * ar2[h];
            g_Wt2[t * 24 + 21] = s;
            g_Wt2[t * 24 + 22] = 0.f;
            g_Wt2[t * 24 + 23] = 0.f;
        } else if (t < 128 + DOUT) {
            g_colsum0[t - 128] = 0.f;
        }
    }
}

// Wt1 fp32 -> bf16 hi/lo fragments for mma.sync m16n8k16 (B col-major k x n):
// frag idx f = (s*NTILES + t)*32 + lane; lane g=lane>>2, q=lane&3.
// reg0 = {B[16s+2q][8t+g], B[16s+2q+1][8t+g]}, reg1 = same with k+8.
__global__ void prep2_kernel() {
    int idx = blockIdx.x * blockDim.x + threadIdx.x;
    if (idx >= BFRAG_CNT) return;
    int lane = idx & 31;
    int t = (idx >> 5) % NTILES;
    int s = idx / (NTILES * 32);
    int g = lane >> 2, q = lane & 3;
    int n = t * 8 + g;
    int k = s * 16 + 2 * q;
    float v0 = g_Wt1[k * 160 + n];
    float v1 = g_Wt1[(k + 1) * 160 + n];
    float v2 = g_Wt1[(k + 8) * 160 + n];
    float v3 = g_Wt1[(k + 9) * 160 + n];
    g_Bfh[idx] = make_uint2(packbf(v0, v1), packbf(v2, v3));
    g_Bfl[idx] = make_uint2(packbf(bflo(v0), bflo(v1)), packbf(bflo(v2), bflo(v3)));
}

// ------------------------- mma.sync big GEMM -------------------------------
// 256 threads = 8 warps (2 mw x 4 nw). BM=64, BN=160, K chunk 64.
// A staged in smem as bf16 hi/lo fragment tables (converted cooperatively).
// Split precision: D += Ah*Bh + Ah*Bl + Al*Bh (fp32 acc).
__global__ __launch_bounds__(256) void gemm_mma(const float* __restrict__ x) {
    extern __shared__ __align__(16) char sm[];
    int tid = threadIdx.x;
    int wid = tid >> 5;
    int lane = tid & 31;
    int mw = wid >> 2;          // 0..1
    int nw = wid & 3;           // 0..3
    int g = lane >> 2, q = lane & 3;
    int rowBase = blockIdx.x * 64;

    float acc[2][5][4];
#pragma unroll
    for (int i = 0; i < 2; i++)
#pragma unroll
        for (int j = 0; j < 5; j++)
#pragma unroll
            for (int k = 0; k < 4; k++) acc[i][j][k] = 0.f;

    for (int ch = 0; ch < NCHUNKS; ch++) {
        __syncthreads();
        // ---- stage A: 64 rows x 64 floats -> bf16 hi/lo fragment tables ----
        {
            int k0 = ch * 64;
#pragma unroll
            for (int i = 0; i < 4; i++) {
                int idx = tid + i * 256;       // 0..1023
                int r = idx >> 4;              // 0..63
                int c4 = idx & 15;             // float4 col
                int row = rowBase + r;
                float4 v = make_float4(0.f, 0.f, 0.f, 0.f);
                if (row < NN) v = *(const float4*)(x + (size_t)row * KDIM + k0 + c4 * 4);
                uint32_t h0 = packbf(v.x, v.y);
                uint32_t h1 = packbf(v.z, v.w);
                uint32_t l0 = packbf(bflo(v.x), bflo(v.y));
                uint32_t l1 = packbf(bflo(v.z), bflo(v.w));
                int p0 = 2 * c4;                       // kpair index in chunk
                int s = p0 >> 3;                       // k-step 0..3
                int j = (((p0 >> 2) & 1) << 1) | ((r >> 3) & 1);
                int lane0 = ((r & 7) << 2) | (p0 & 3);
                int mt = r >> 4;                       // m16 tile 0..3
                int base = ((s * 4 + mt) * 32) * 16 + j * 4;
                *(uint32_t*)(sm + OFF_AF_H + base + lane0 * 16) = h0;
                *(uint32_t*)(sm + OFF_AF_H + base + (lane0 + 1) * 16) = h1;
                *(uint32_t*)(sm + OFF_AF_L + base + lane0 * 16) = l0;
                *(uint32_t*)(sm + OFF_AF_L + base + (lane0 + 1) * 16) = l1;
            }
        }
        // ---- stage B: copy this chunk's fragment tables (hi + lo) ----
        {
            const uint4* srcH = reinterpret_cast<const uint4*>(g_Bfh) + ch * 1280;
            const uint4* srcL = reinterpret_cast<const uint4*>(g_Bfl) + ch * 1280;
#pragma unroll
            for (int i = 0; i < 5; i++) {
                int s = tid + i * 256;         // 0..1279
                *(uint4*)(sm + OFF_B_H + s * 16) = srcH[s];
                *(uint4*)(sm + OFF_B_L + s * 16) = srcL[s];
            }
        }
        __syncthreads();

        // ---- compute 4 k-steps ----
#pragma unroll
        for (int s = 0; s < CH_STEPS; s++) {
            uint4 ah[2], al[2];
#pragma unroll
            for (int mt = 0; mt < 2; mt++) {
                int tile = s * 4 + mw * 2 + mt;
                ah[mt] = *(uint4*)(sm + OFF_AF_H + (tile * 32 + lane) * 16);
                al[mt] = *(uint4*)(sm + OFF_AF_L + (tile * 32 + lane) * 16);
            }
#pragma unroll
            for (int nt = 0; nt < 5; nt++) {
                int fi = (s * NTILES + nw * 5 + nt) * 32 + lane;
                uint2 bh = *(uint2*)(sm + OFF_B_H + fi * 8);
                uint2 bl = *(uint2*)(sm + OFF_B_L + fi * 8);
#pragma unroll
                for (int mt = 0; mt < 2; mt++) {
                    mma_bf16(acc[mt][nt][0], acc[mt][nt][1], acc[mt][nt][2], acc[mt][nt][3],
                             ah[mt].x, ah[mt].y, ah[mt].z, ah[mt].w, bh.x, bh.y);
                    mma_bf16(acc[mt][nt][0], acc[mt][nt][1], acc[mt][nt][2], acc[mt][nt][3],
                             ah[mt].x, ah[mt].y, ah[mt].z, ah[mt].w, bl.x, bl.y);
                    mma_bf16(acc[mt][nt][0], acc[mt][nt][1], acc[mt][nt][2], acc[mt][nt][3],
                             al[mt].x, al[mt].y, al[mt].z, al[mt].w, bh.x, bh.y);
                }
            }
        }
    }

    // ---- epilogue ----
#pragma unroll
    for (int mt = 0; mt < 2; mt++) {
#pragma unroll
        for (int half = 0; half < 2; half++) {
            int row = rowBase + (mw * 2 + mt) * 16 + half * 8 + g;
            if (row >= NN) continue;
#pragma unroll
            for (int nt = 0; nt < 5; nt++) {
                int col = nw * 40 + nt * 8 + 2 * q;
                float c0 = acc[mt][nt][half * 2 + 0];
                float c1 = acc[mt][nt][half * 2 + 1];
                if (col < HID) {
                    *(float2*)&g_xl1[(size_t)row * HID + col] = make_float2(c0, c1);
                } else {
                    int cc = col - HID;
                    if (cc < DOUT) {
                        *(float2*)&g_s0[(size_t)row * DOUT + cc] = make_float2(c0, c1);
                    } else if (cc == DOUT) {
                        g_el1[row] = c0;
                        g_er1[row] = c1;
                    }
                }
            }
        }
    }
}

// ------------------------- column-softmax reduce ---------------------------
__global__ void colsum_kernel(const float* __restrict__ b0) {
    __shared__ float bs[DOUT];
    int tid = threadIdx.x;
    if (tid < DOUT) bs[tid] = 0.f;
    __syncthreads();
    float ls[DOUT];
#pragma unroll
    for (int c = 0; c < DOUT; c++) ls[c] = 0.f;
    for (int n = blockIdx.x * blockDim.x + tid; n < NN; n += gridDim.x * blockDim.x) {
#pragma unroll
        for (int c = 0; c < DOUT; c++) ls[c] += expf(g_s0[n * DOUT + c] + b0[c]);
    }
#pragma unroll
    for (int c = 0; c < DOUT; c++) {
#pragma unroll
        for (int off = 16; off; off >>= 1)
            ls[c] += __shfl_xor_sync(0xffffffffu, ls[c], off);
    }
    if ((tid & 31) == 0) {
#pragma unroll
        for (int c = 0; c < DOUT; c++) atomicAdd(&bs[c], ls[c]);
    }
    __syncthreads();
    if (tid < DOUT) atomicAdd(&g_colsum0[tid], bs[tid]);
}

// ------------------------- CSR build ---------------------------------------
__global__ void deg_count(const void* __restrict__ ei) {
    int i = blockIdx.x * blockDim.x + threadIdx.x;
    if (i >= EE) return;
    int d = edge_at(ei, EE + i);
    atomicAdd(&g_deg[d], 1);
}

__global__ void scanA_kernel() {
    __shared__ int warpsum[16];
    int b = blockIdx.x, t = threadIdx.x;
    int i = b * 512 + t;
    int v = (i < NN) ? g_deg[i] : 0;
    int x = v;
#pragma unroll
    for (int off = 1; off < 32; off <<= 1) {
        int y = __shfl_up_sync(0xffffffffu, x, off);
        if ((t & 31) >= off) x += y;
    }
    if ((t & 31) == 31) warpsum[t >> 5] = x;
    __syncthreads();
    if (t < 16) {
        int s = warpsum[t];
#pragma unroll
        for (int off = 1; off < 16; off <<= 1) {
            int y = __shfl_up_sync(0xffffu, s, off);
            if (t >= off) s += y;
        }
        warpsum[t] = s;
    }
    __syncthreads();
    int incl = x + ((t >> 5) ? warpsum[(t >> 5) - 1] : 0);
    if (i < NN) g_rowoff[i] = incl - v;
    if (t == 511) g_bsum[b] = incl;
}

__global__ void scanB_kernel() {
    __shared__ int warpsum[4];
    int t = threadIdx.x;
    int v = (t < NB_SCAN) ? g_bsum[t] : 0;
    int x = v;
#pragma unroll
    for (int off = 1; off < 32; off <<= 1) {
        int y = __shfl_up_sync(0xffffffffu, x, off);
        if ((t & 31) >= off) x += y;
    }
    if ((t & 31) == 31) warpsum[t >> 5] = x;
    __syncthreads();
    if (t < 4) {
        int s = warpsum[t];
#pragma unroll
        for (int off = 1; off < 4; off <<= 1) {
            int y = __shfl_up_sync(0xfu, s, off);
            if (t >= off) s += y;
        }
        warpsum[t] = s;
    }
    __syncthreads();
    int incl = x + ((t >> 5) ? warpsum[(t >> 5) - 1] : 0);
    if (t < NB_SCAN) g_boff[t] = incl - v;
}

__global__ void scanC_kernel() {
    int b = blockIdx.x, t = threadIdx.x;
    int i = b * 512 + t;
    if (i < NN) {
        int o = g_rowoff[i] + g_boff[b];
        g_rowoff[i] = o;
        g_cursor[i] = o;
    }
    if (b == 0 && t == 0) g_rowoff[NN] = EE;
}

__global__ void scatter_kernel(const void* __restrict__ ei) {
    int i = blockIdx.x * blockDim.x + threadIdx.x;
    if (i >= EE) return;
    int s = edge_at(ei, i);
    int d = edge_at(ei, EE + i);
    int pos = atomicAdd(&g_cursor[d], 1);
    g_csrc[pos] = s;
}

// ------------------------- gather (layer 1) --------------------------------
__global__ __launch_bounds__(256) void gather1_kernel() {
    int warp = (blockIdx.x * blockDim.x + threadIdx.x) >> 5;
    int lane = threadIdx.x & 31;
    if (warp >= NN) return;
    int dst = warp;
    int beg = g_rowoff[dst];
    int end = g_rowoff[dst + 1];
    float er = g_er1[dst];

    float denom = 0.f;
    for (int j = beg + lane; j < end; j += 32) {
        int s = g_csrc[j];
        denom += expf(leaky(g_el1[s] + er));
    }
#pragma unroll
    for (int off = 16; off; off >>= 1)
        denom += __shfl_xor_sync(0xffffffffu, denom, off);
    float inv = __fdividef(1.f, denom + 1e-16f);

    float4 acc = make_float4(0.f, 0.f, 0.f, 0.f);
    for (int j = beg; j < end; j++) {
        int s = g_csrc[j];
        float a = expf(leaky(g_el1[s] + er)) * inv;
        float4 v = *(const float4*)&g_xl1[(size_t)s * HID + lane * 4];
        acc.x += a * v.x; acc.y += a * v.y; acc.z += a * v.z; acc.w += a * v.w;
    }
    *(float4*)&g_agg1[(size_t)dst * HID + lane * 4] = acc;
}

// ------------------------- layer-2 GEMM ------------------------------------
__global__ __launch_bounds__(128) void gemm2_kernel(const float* __restrict__ b1) {
    __shared__ float Ws[HID * 24];
    __shared__ float Hs[128][33];
    int tid = threadIdx.x;
    for (int i = tid; i < HID * 24; i += 128) Ws[i] = g_Wt2[i];
    int rt = tid >> 3;
    int ct = tid & 7;
    int rowBase = blockIdx.x * 128;
    float acc[8][3] = {};

    for (int k0 = 0; k0 < HID; k0 += 32) {
        __syncthreads();
#pragma unroll
        for (int l = 0; l < 8; l++) {
            int idx = tid + l * 128;
            int r = idx >> 3;
            int kc = idx & 7;
            int row = rowBase + r;
            float4 v = make_float4(0.f, 0.f, 0.f, 0.f);
            if (row < NN) v = *(const float4*)&g_agg1[(size_t)row * HID + k0 + kc * 4];
            int kb = k0 + kc * 4;
            Hs[r][kc * 4 + 0] = eluf(v.x + b1[kb + 0]);
            Hs[r][kc * 4 + 1] = eluf(v.y + b1[kb + 1]);
            Hs[r][kc * 4 + 2] = eluf(v.z + b1[kb + 2]);
            Hs[r][kc * 4 + 3] = eluf(v.w + b1[kb + 3]);
        }
        __syncthreads();
#pragma unroll
        for (int kk = 0; kk < 32; kk++) {
            float w0 = Ws[(k0 + kk) * 24 + ct * 3 + 0];
            float w1 = Ws[(k0 + kk) * 24 + ct * 3 + 1];
            float w2 = Ws[(k0 + kk) * 24 + ct * 3 + 2];
#pragma unroll
            for (int i = 0; i < 8; i++) {
                float a = Hs[rt * 8 + i][kk];
                acc[i][0] += a * w0;
                acc[i][1] += a * w1;
                acc[i][2] += a * w2;
            }
        }
    }
#pragma unroll
    for (int i = 0; i < 8; i++) {
        int row = rowBase + rt * 8 + i;
        if (row < NN) {
#pragma unroll
            for (int j = 0; j < 3; j++) {
                int c = ct * 3 + j;
                float vv = acc[i][j];
                if (c < DOUT) {
                    g_xl2[row * DOUT + c] = vv;
                } else if (c == 20) {
                    g_el2[row] = vv;
                } else if (c == 21) {
                    g_er2[row] = vv;
                }
            }
        }
    }
}

// ------------------------- gather (layer 2) + final combine ----------------
__global__ __launch_bounds__(256) void gather2_kernel(const float* __restrict__ b0,
                                                      const float* __restrict__ b2,
                                                      float* __restrict__ out) {
    int warp = (blockIdx.x * blockDim.x + threadIdx.x) >> 5;
    int lane = threadIdx.x & 31;
    if (warp >= NN) return;
    int dst = warp;
    int beg = g_rowoff[dst];
    int end = g_rowoff[dst + 1];
    float er = g_er2[dst];

    float denom = 0.f;
    for (int j = beg + lane; j < end; j += 32) {
        int s = g_csrc[j];
        denom += expf(leaky(g_el2[s] + er));
    }
#pragma unroll
    for (int off = 16; off; off >>= 1)
        denom += __shfl_xor_sync(0xffffffffu, denom, off);
    float inv = __fdividef(1.f, denom + 1e-16f);

    float acc = 0.f;
    for (int j = beg; j < end; j++) {
        int s = g_csrc[j];
        float a = expf(leaky(g_el2[s] + er)) * inv;
        if (lane < DOUT) acc += a * g_xl2[s * DOUT + lane];
    }
    float ev = 0.f;
    if (lane < DOUT) ev = expf(acc + b2[lane]);
    float rs = ev;
#pragma unroll
    for (int off = 16; off; off >>= 1)
        rs += __shfl_xor_sync(0xffffffffu, rs, off);
    float ir = __fdividef(1.f, rs);
    if (lane < DOUT) {
        float p0 = expf(g_s0[dst * DOUT + lane] + b0[lane]) *
                   __fdividef(1.f, g_colsum0[lane]);
        out[dst * DOUT + lane] = p0 * ev * ir;
    }
}

// ------------------------- launch ------------------------------------------
extern "C" void kernel_launch(void* const* d_in, const int* in_sizes, int n_in,
                              void* d_out, int out_size) {
    const float* x        = (const float*)d_in[0];
    const void* ei        = d_in[1];
    const float* W0       = (const float*)d_in[2];
    const float* b0       = (const float*)d_in[3];
    const float* g1Wl     = (const float*)d_in[4];
    const float* g1Wr     = (const float*)d_in[5];
    const float* g1al     = (const float*)d_in[6];
    const float* g1ar     = (const float*)d_in[7];
    const float* g1b      = (const float*)d_in[8];
    const float* g2Wl     = (const float*)d_in[9];
    const float* g2Wr     = (const float*)d_in[10];
    const float* g2al     = (const float*)d_in[11];
    const float* g2ar     = (const float*)d_in[12];
    const float* g2b      = (const float*)d_in[13];
    float* out            = (float*)d_out;

    cudaFuncSetAttribute(gemm_mma, cudaFuncAttributeMaxDynamicSharedMemorySize, SMEM_SZ);

    detect_kernel<<<1, 32>>>(ei);
    prep_kernel<<<161, 512>>>(W0, g1Wl, g1Wr, g1al, g1ar, g2Wl, g2Wr, g2al, g2ar);
    prep2_kernel<<<(BFRAG_CNT + 255) / 256, 256>>>();
    gemm_mma<<<(NN + 63) / 64, 256, SMEM_SZ>>>(x);
    colsum_kernel<<<400, 256>>>(b0);
    deg_count<<<(EE + 255) / 256, 256>>>(ei);
    scanA_kernel<<<NB_SCAN, 512>>>();
    scanB_kernel<<<1, 128>>>();
    scanC_kernel<<<NB_SCAN, 512>>>();
    scatter_kernel<<<(EE + 255) / 256, 256>>>(ei);
    gather1_kernel<<<(NN * 32 + 255) / 256, 256>>>();
    gemm2_kernel<<<(NN + 127) / 128, 128>>>(g1b);
    gather2_kernel<<<(NN * 32 + 255) / 256, 256>>>(b0, g2b, out);
}